// round 11
// baseline (speedup 1.0000x reference)
#include <cuda_runtime.h>
#include <cstdint>

#define BATCH 512
#define IN0   784
#define HID   1024
#define NOUT  10
#define NT    32
#define GCAP  256   // per-group row-list capacity (multiple of 2)
#define KSPLIT 7    // 784 = 7 * 112

// Scratch (no cudaMalloc allowed): device globals.
__device__ float g_part[KSPLIT * BATCH * HID]; // split-K partial sums
__device__ float g_w1t[(HID + 1) * HID];       // W1^T + zero pad row (id 1024)
__device__ float g_w2t[HID * 16];              // W2 transposed, stride 16

typedef unsigned long long ull;

// ---- packed fp32x2 helpers (each = two independent exact rn fp32 ops) ----
__device__ __forceinline__ ull addf32x2(ull a, ull b) {
    ull r; asm("add.rn.f32x2 %0, %1, %2;" : "=l"(r) : "l"(a), "l"(b)); return r;
}
__device__ __forceinline__ ull fmaf32x2(ull a, ull b, ull c) {
    ull r; asm("fma.rn.f32x2 %0, %1, %2, %3;" : "=l"(r) : "l"(a), "l"(b), "l"(c)); return r;
}
__device__ __forceinline__ ull pkf2(float lo, float hi) {
    ull r; asm("mov.b64 %0, {%1, %2};" : "=l"(r) : "f"(lo), "f"(hi)); return r;
}
__device__ __forceinline__ void unpkf2(ull v, float& lo, float& hi) {
    asm("mov.b64 {%0, %1}, %2;" : "=f"(lo), "=f"(hi) : "l"(v));
}

// Predicated scatter: for T in [0,8): if (m & (1<<T)) { a0[T]+=w0; a1[T]+=w1 }
// One setp shared by both packed adds; PTX predication (no branches).
template <int T>
struct Scat {
    static __device__ __forceinline__ void run(ull* a0, ull* a1,
                                               unsigned m, ull w0, ull w1) {
        asm("{\n\t"
            ".reg .pred p;\n\t"
            ".reg .b32 t;\n\t"
            "and.b32 t, %2, %5;\n\t"
            "setp.ne.b32 p, t, 0;\n\t"
            "@p add.rn.f32x2 %0, %0, %3;\n\t"
            "@p add.rn.f32x2 %1, %1, %4;\n\t"
            "}"
            : "+l"(a0[T]), "+l"(a1[T])
            : "r"(m), "l"(w0), "l"(w1), "n"(1u << T));
        Scat<T + 1>::run(a0, a1, m, w0, w1);
    }
};
template <>
struct Scat<8> {
    static __device__ __forceinline__ void run(ull*, ull*, unsigned, ull, ull) {}
};

// ---------------------------------------------------------------------------
// prep (R7-proven, 26.1us): blocks [0,448)   -> split-K gemm0, 64x128, FMA2
//                           blocks [448,704) -> W1/W2 transpose (float4 I/O)
// ---------------------------------------------------------------------------
__global__ void __launch_bounds__(256) prep_kernel(
    const float* __restrict__ X,     // [512,784]
    const float* __restrict__ W0,    // [1024,784]
    const float* __restrict__ W1,    // [1024,1024]
    const float* __restrict__ W2)    // [10,1024]
{
    __shared__ __align__(16) float sm[6400];

    const int blk = blockIdx.x;
    const int tid = threadIdx.x;

    if (blk >= 448) {
        float (*tile)[65] = (float (*)[65])sm;
        const int tb = blk - 448;
        const int bx = (tb & 15) * 64, by = (tb >> 4) * 64;
        const int tx = tid & 15, ty = tid >> 4;
#pragma unroll
        for (int r = 0; r < 4; r++) {
            const int row = ty + r * 16;
            float4 v = *(const float4*)(W1 + (by + row) * HID + bx + tx * 4);
            tile[row][tx * 4 + 0] = v.x;
            tile[row][tx * 4 + 1] = v.y;
            tile[row][tx * 4 + 2] = v.z;
            tile[row][tx * 4 + 3] = v.w;
        }
        __syncthreads();
#pragma unroll
        for (int r = 0; r < 4; r++) {
            const int row = ty + r * 16;
            float4 v;
            v.x = tile[tx * 4 + 0][row];
            v.y = tile[tx * 4 + 1][row];
            v.z = tile[tx * 4 + 2][row];
            v.w = tile[tx * 4 + 3][row];
            *(float4*)(g_w1t + (unsigned)(bx + row) * HID + by + tx * 4) = v;
        }
        if (tb == 0) {
            // zero pad row (id 1024) used by group-list padding in snn
            ((float4*)(g_w1t + HID * HID))[tid] = make_float4(0.f, 0.f, 0.f, 0.f);
#pragma unroll
            for (int r = 0; r < 4; r++) {
                const int i = tid + r * 256;
#pragma unroll
                for (int j = 0; j < NOUT; j++)
                    g_w2t[i * 16 + j] = W2[j * HID + i];
            }
        }
        return;
    }

    // split-K gemm0: 64x128 tile, BK=16, K-range 112
    const int s  = blk >> 6;
    const int r_ = blk & 63;
    const int bm = (r_ >> 3) * 64;
    const int bn = (r_ & 7) * 128;
    const int kbeg = s * 112;

    const int tx = tid & 15, ty = tid >> 4;
    const int lrow = tid >> 2, lc = (tid & 3) * 4;

    const float* Xp  = X  + (bm + lrow) * IN0 + kbeg + lc;
    const float* Wp0 = W0 + (bn + lrow) * IN0 + kbeg + lc;
    const float* Wp1 = Wp0 + 64 * IN0;

    ull acc[4][4];
#pragma unroll
    for (int r = 0; r < 4; r++)
#pragma unroll
        for (int p = 0; p < 4; p++) acc[r][p] = 0ull;

    float4 a_r  = *(const float4*)Xp;
    float4 b_r0 = *(const float4*)Wp0;
    float4 b_r1 = *(const float4*)Wp1;
    {
        float* As = sm;
        float* Bs = sm + 1088;
        As[(lc + 0) * 68 + lrow] = a_r.x;  As[(lc + 1) * 68 + lrow] = a_r.y;
        As[(lc + 2) * 68 + lrow] = a_r.z;  As[(lc + 3) * 68 + lrow] = a_r.w;
        Bs[(lc + 0) * 132 + lrow] = b_r0.x; Bs[(lc + 1) * 132 + lrow] = b_r0.y;
        Bs[(lc + 2) * 132 + lrow] = b_r0.z; Bs[(lc + 3) * 132 + lrow] = b_r0.w;
        Bs[(lc + 0) * 132 + 64 + lrow] = b_r1.x; Bs[(lc + 1) * 132 + 64 + lrow] = b_r1.y;
        Bs[(lc + 2) * 132 + 64 + lrow] = b_r1.z; Bs[(lc + 3) * 132 + 64 + lrow] = b_r1.w;
    }
    __syncthreads();

#pragma unroll 1
    for (int kt = 0; kt < 7; kt++) {
        const float* As = sm + (kt & 1) * 3200;
        const float* Bs = As + 1088;

        if (kt < 6) {
            a_r  = *(const float4*)(Xp  + (kt + 1) * 16);
            b_r0 = *(const float4*)(Wp0 + (kt + 1) * 16);
            b_r1 = *(const float4*)(Wp1 + (kt + 1) * 16);
        }

#pragma unroll
        for (int kk = 0; kk < 16; kk++) {
            const float4 a = *(const float4*)(As + kk * 68 + ty * 4);
            const ulonglong2 bl = *(const ulonglong2*)(Bs + kk * 132 + tx * 4);
            const ulonglong2 bh = *(const ulonglong2*)(Bs + kk * 132 + 64 + tx * 4);
            const float av[4] = {a.x, a.y, a.z, a.w};
#pragma unroll
            for (int r = 0; r < 4; r++) {
                const ull ar = pkf2(av[r], av[r]);
                acc[r][0] = fmaf32x2(ar, bl.x, acc[r][0]);
                acc[r][1] = fmaf32x2(ar, bl.y, acc[r][1]);
                acc[r][2] = fmaf32x2(ar, bh.x, acc[r][2]);
                acc[r][3] = fmaf32x2(ar, bh.y, acc[r][3]);
            }
        }

        if (kt < 6) {
            float* An = sm + ((kt + 1) & 1) * 3200;
            float* Bn = An + 1088;
            An[(lc + 0) * 68 + lrow] = a_r.x;  An[(lc + 1) * 68 + lrow] = a_r.y;
            An[(lc + 2) * 68 + lrow] = a_r.z;  An[(lc + 3) * 68 + lrow] = a_r.w;
            Bn[(lc + 0) * 132 + lrow] = b_r0.x; Bn[(lc + 1) * 132 + lrow] = b_r0.y;
            Bn[(lc + 2) * 132 + lrow] = b_r0.z; Bn[(lc + 3) * 132 + lrow] = b_r0.w;
            Bn[(lc + 0) * 132 + 64 + lrow] = b_r1.x; Bn[(lc + 1) * 132 + 64 + lrow] = b_r1.y;
            Bn[(lc + 2) * 132 + 64 + lrow] = b_r1.z; Bn[(lc + 3) * 132 + 64 + lrow] = b_r1.w;
            __syncthreads();
        }
    }

    float* outb = g_part + (unsigned)s * BATCH * HID;
#pragma unroll
    for (int r = 0; r < 4; r++) {
        float* orow = outb + (unsigned)(bm + ty * 4 + r) * HID + bn;
        float lo, hi;
        unpkf2(acc[r][0], lo, hi); orow[tx * 4]          = lo; orow[tx * 4 + 1]      = hi;
        unpkf2(acc[r][1], lo, hi); orow[tx * 4 + 2]      = lo; orow[tx * 4 + 3]      = hi;
        unpkf2(acc[r][2], lo, hi); orow[64 + tx * 4]     = lo; orow[64 + tx * 4 + 1] = hi;
        unpkf2(acc[r][3], lo, hi); orow[64 + tx * 4 + 2] = lo; orow[64 + tx * 4 + 3] = hi;
    }
}

// ---------------------------------------------------------------------------
// Fused snn (G=8 group scatter): one block (256 thr) per batch b.
// Thread owns 4 adjacent neurons. Per group of 8 timesteps: compact row list
// (idx | submask<<16), each row loaded ONCE (LDG.128) and scattered into
// 8 per-t accumulators (16 ull = 32 regs) via predicated packed adds.
// Then 8 LIF steps; layer-2 in-block from smem masks.
// ---------------------------------------------------------------------------
__global__ void __launch_bounds__(256, 4) snn_kernel(
    const float* __restrict__ b0,
    const float* __restrict__ b1,
    const float* __restrict__ b2,
    float* __restrict__ out)  // [512,10]
{
    const int b = blockIdx.x;
    const int tid = threadIdx.x;
    const int lane = tid & 31, warp = tid >> 5;   // 8 warps

    __shared__ unsigned       mask1[NT][32];
    __shared__ unsigned short uni_idx[HID];
    __shared__ unsigned       uni_tm[HID];
    __shared__ unsigned       glist[4][GCAP];    // idx | submask<<16
    __shared__ int            gn[4];
    __shared__ int            segCnt[32], segBal[32], segOff[32], sh_nU;
    __shared__ float          c2part[NT][NOUT];

    // ---- phase 1: combine split-K partials, layer-0 LIF ----
    float4 c0 = *(const float4*)(b0 + 4 * tid);
#pragma unroll
    for (int s = 0; s < KSPLIT; s++) {
        float4 p = *(const float4*)(g_part + ((unsigned)s * BATCH + b) * HID + 4 * tid);
        c0.x += p.x; c0.y += p.y; c0.z += p.z; c0.w += p.w;
    }
    float c0a[4] = {c0.x, c0.y, c0.z, c0.w};
    unsigned tm0[4] = {0u, 0u, 0u, 0u};
    {
        float v0[4] = {0.f, 0.f, 0.f, 0.f};
#pragma unroll
        for (int t = 0; t < NT; t++) {
#pragma unroll
            for (int j = 0; j < 4; j++) {
                v0[j] += (c0a[j] - v0[j]) * 0.5f;
                if (v0[j] >= 1.0f) { tm0[j] |= (1u << t); v0[j] = 0.f; }
            }
        }
    }

    // ---- phase 2a: union list of ever-spiking layer-0 neurons ----
#pragma unroll
    for (int j = 0; j < 4; j++) {
        unsigned bal = __ballot_sync(0xffffffffu, tm0[j] != 0u);
        if (lane == 0) {
            segCnt[warp * 4 + j] = __popc(bal);
            segBal[warp * 4 + j] = (int)bal;
        }
    }
    __syncthreads();
    if (warp == 0) {
        int c = segCnt[lane];
        int inc = c;
#pragma unroll
        for (int d = 1; d < 32; d <<= 1) {
            int y = __shfl_up_sync(0xffffffffu, inc, d);
            if (lane >= d) inc += y;
        }
        segOff[lane] = inc - c;
        if (lane == 31) sh_nU = inc;
    }
    __syncthreads();
#pragma unroll
    for (int j = 0; j < 4; j++) {
        if (tm0[j] != 0u) {
            const int s = warp * 4 + j;
            const int pos = segOff[s] +
                __popc((unsigned)segBal[s] & ((1u << lane) - 1u));
            uni_idx[pos] = (unsigned short)(4 * tid + j);
            uni_tm[pos]  = tm0[j];
        }
    }
    __syncthreads();

    // ---- phase 2b: group lists (warp g in [0,4) builds group g) ----
    const int nU = sh_nU;
    if (warp < 4) {
        const int g = warp;
        int base = 0;
        for (int c = 0; c < nU; c += 32) {
            const int k = c + lane;
            unsigned tmv = (k < nU) ? uni_tm[k] : 0u;
            unsigned sub = (tmv >> (8 * g)) & 0xFFu;
            bool p = sub != 0u;
            unsigned bal = __ballot_sync(0xffffffffu, p);
            if (p) {
                int pos = base + __popc(bal & ((1u << lane) - 1u));
                if (pos < GCAP - 2)
                    glist[g][pos] = (unsigned)uni_idx[k] | (sub << 16);
            }
            base += __popc(bal);
        }
        if (base > GCAP - 2) base = GCAP - 2;
        const int padded = (base + 1) & ~1;
        if (lane == 0) {
            for (int p = base; p < padded; p++)
                glist[g][p] = (unsigned)HID;   // zero row, submask 0
            gn[g] = padded;
        }
    }
    __syncthreads();

    // ---- phase 3: group loop — load rows once, scatter into 8 acc ----
    const ull b1p0 = pkf2(b1[4 * tid],     b1[4 * tid + 1]);
    const ull b1p1 = pkf2(b1[4 * tid + 2], b1[4 * tid + 3]);
    float v1[4] = {0.f, 0.f, 0.f, 0.f};

#pragma unroll 1
    for (int g = 0; g < 4; g++) {
        ull a0[8], a1[8];
#pragma unroll
        for (int i = 0; i < 8; i++) { a0[i] = b1p0; a1[i] = b1p1; }

        const int n2 = gn[g] >> 1;
        const uint2* gl = (const uint2*)&glist[g][0];
#pragma unroll 1
        for (int k = 0; k < n2; k++) {
            const uint2 e = gl[k];
            const unsigned i0 = e.x & 0xFFFFu, m0 = e.x >> 16;
            const unsigned i1 = e.y & 0xFFFFu, m1 = e.y >> 16;
            ulonglong2 r0 = __ldg((const ulonglong2*)(g_w1t + i0 * HID) + tid);
            ulonglong2 r1 = __ldg((const ulonglong2*)(g_w1t + i1 * HID) + tid);
            Scat<0>::run(a0, a1, m0, r0.x, r0.y);
            Scat<0>::run(a0, a1, m1, r1.x, r1.y);
        }

        // 8 LIF steps for t = 8g .. 8g+7
#pragma unroll
        for (int i = 0; i < 8; i++) {
            const int t = g * 8 + i;
            float c1[4];
            unpkf2(a0[i], c1[0], c1[1]);
            unpkf2(a1[i], c1[2], c1[3]);
#pragma unroll
            for (int j = 0; j < 4; j++) {
                v1[j] += (c1[j] - v1[j]) * 0.5f;
                bool s = v1[j] >= 1.0f;
                unsigned bal = __ballot_sync(0xffffffffu, s);
                if (s) v1[j] = 0.f;
                if (lane == 0) mask1[t][warp * 4 + j] = bal;
            }
        }
    }
    __syncthreads();

    // ---- phase 4: layer-2 partial currents (warp w -> t = 4w..4w+3) ----
    // word W, bit l -> neuron 128*(W>>2) + 4*l + (W&3)
#pragma unroll
    for (int h = 0; h < 4; h++) {
        const int t = warp * 4 + h;
        unsigned m = mask1[t][lane];
        float c2 = 0.f;
        unsigned act = __ballot_sync(0xffffffffu, m != 0u);
        while (act) {
            const int src = __ffs(act) - 1;
            act &= act - 1;
            unsigned mw = __shfl_sync(0xffffffffu, m, src);
            const int nb = 128 * (src >> 2) + (src & 3);
            while (mw) {
                const int bit = __ffs(mw) - 1;
                mw &= mw - 1;
                if (lane < NOUT)
                    c2 += g_w2t[(unsigned)(nb + 4 * bit) * 16 + lane];
            }
        }
        if (lane < NOUT) c2part[t][lane] = c2;
    }
    __syncthreads();

    // ---- phase 5: layer-2 LIF recurrence + spike count ----
    if (warp == 0 && lane < NOUT) {
        const float b2r = b2[lane];
        float v2 = 0.f, cnt = 0.f;
#pragma unroll
        for (int t = 0; t < NT; t++) {
            const float c2 = c2part[t][lane] + b2r;
            v2 += (c2 - v2) * 0.5f;
            if (v2 >= 1.0f) { cnt += 1.0f; v2 = 0.f; }
        }
        out[b * NOUT + lane] = cnt;
    }
}

// ---------------------------------------------------------------------------
extern "C" void kernel_launch(void* const* d_in, const int* in_sizes, int n_in,
                              void* d_out, int out_size) {
    const float* x  = (const float*)d_in[0];  // [512,784]
    const float* W0 = (const float*)d_in[1];  // [1024,784]
    const float* b0 = (const float*)d_in[2];  // [1024]
    const float* W1 = (const float*)d_in[3];  // [1024,1024]
    const float* b1 = (const float*)d_in[4];  // [1024]
    const float* W2 = (const float*)d_in[5];  // [10,1024]
    const float* b2 = (const float*)d_in[6];  // [10]
    float* out = (float*)d_out;               // [512,10] float32

    prep_kernel<<<704, 256>>>(x, W0, W1, W2);
    snn_kernel<<<BATCH, 256>>>(b0, b1, b2, out);
}

// round 12
// speedup vs baseline: 1.4672x; 1.4672x over previous
#include <cuda_runtime.h>
#include <cstdint>

#define BATCH 512
#define IN0   784
#define HID   1024
#define NOUT  10
#define NT    32
#define LCAP  128   // per-timestep spike-list capacity (multiple of 8)
#define KSPLIT 7    // 784 = 7 * 112

// Scratch (no cudaMalloc allowed): device globals.
__device__ float g_part[KSPLIT * BATCH * HID]; // split-K partial sums
__device__ float g_w1t[(HID + 1) * HID];       // W1^T + zero pad row (id 1024)
__device__ float g_w2t[HID * 16];              // W2 transposed, stride 16

typedef unsigned long long ull;

// ---- packed fp32x2 helpers (each = two independent exact rn fp32 ops) ----
__device__ __forceinline__ ull addf32x2(ull a, ull b) {
    ull r; asm("add.rn.f32x2 %0, %1, %2;" : "=l"(r) : "l"(a), "l"(b)); return r;
}
__device__ __forceinline__ ull fmaf32x2(ull a, ull b, ull c) {
    ull r; asm("fma.rn.f32x2 %0, %1, %2, %3;" : "=l"(r) : "l"(a), "l"(b), "l"(c)); return r;
}
__device__ __forceinline__ ull pkf2(float lo, float hi) {
    ull r; asm("mov.b64 %0, {%1, %2};" : "=l"(r) : "f"(lo), "f"(hi)); return r;
}
__device__ __forceinline__ void unpkf2(ull v, float& lo, float& hi) {
    asm("mov.b64 {%0, %1}, %2;" : "=f"(lo), "=f"(hi) : "l"(v));
}

// ---------------------------------------------------------------------------
// prep (R7-proven, 26.1us): blocks [0,448)   -> split-K gemm0, 64x128, FMA2
//                           blocks [448,704) -> W1/W2 transpose (float4 I/O)
// ---------------------------------------------------------------------------
__global__ void __launch_bounds__(256) prep_kernel(
    const float* __restrict__ X,     // [512,784]
    const float* __restrict__ W0,    // [1024,784]
    const float* __restrict__ W1,    // [1024,1024]
    const float* __restrict__ W2)    // [10,1024]
{
    __shared__ __align__(16) float sm[6400];

    const int blk = blockIdx.x;
    const int tid = threadIdx.x;

    if (blk >= 448) {
        float (*tile)[65] = (float (*)[65])sm;
        const int tb = blk - 448;
        const int bx = (tb & 15) * 64, by = (tb >> 4) * 64;
        const int tx = tid & 15, ty = tid >> 4;
#pragma unroll
        for (int r = 0; r < 4; r++) {
            const int row = ty + r * 16;
            float4 v = *(const float4*)(W1 + (by + row) * HID + bx + tx * 4);
            tile[row][tx * 4 + 0] = v.x;
            tile[row][tx * 4 + 1] = v.y;
            tile[row][tx * 4 + 2] = v.z;
            tile[row][tx * 4 + 3] = v.w;
        }
        __syncthreads();
#pragma unroll
        for (int r = 0; r < 4; r++) {
            const int row = ty + r * 16;
            float4 v;
            v.x = tile[tx * 4 + 0][row];
            v.y = tile[tx * 4 + 1][row];
            v.z = tile[tx * 4 + 2][row];
            v.w = tile[tx * 4 + 3][row];
            *(float4*)(g_w1t + (unsigned)(bx + row) * HID + by + tx * 4) = v;
        }
        if (tb == 0) {
            // zero pad row (id 1024) used by list padding in snn
            ((float4*)(g_w1t + HID * HID))[tid] = make_float4(0.f, 0.f, 0.f, 0.f);
#pragma unroll
            for (int r = 0; r < 4; r++) {
                const int i = tid + r * 256;
#pragma unroll
                for (int j = 0; j < NOUT; j++)
                    g_w2t[i * 16 + j] = W2[j * HID + i];
            }
        }
        return;
    }

    // split-K gemm0: 64x128 tile, BK=16, K-range 112
    const int s  = blk >> 6;
    const int r_ = blk & 63;
    const int bm = (r_ >> 3) * 64;
    const int bn = (r_ & 7) * 128;
    const int kbeg = s * 112;

    const int tx = tid & 15, ty = tid >> 4;
    const int lrow = tid >> 2, lc = (tid & 3) * 4;

    const float* Xp  = X  + (bm + lrow) * IN0 + kbeg + lc;
    const float* Wp0 = W0 + (bn + lrow) * IN0 + kbeg + lc;
    const float* Wp1 = Wp0 + 64 * IN0;

    ull acc[4][4];
#pragma unroll
    for (int r = 0; r < 4; r++)
#pragma unroll
        for (int p = 0; p < 4; p++) acc[r][p] = 0ull;

    float4 a_r  = *(const float4*)Xp;
    float4 b_r0 = *(const float4*)Wp0;
    float4 b_r1 = *(const float4*)Wp1;
    {
        float* As = sm;
        float* Bs = sm + 1088;
        As[(lc + 0) * 68 + lrow] = a_r.x;  As[(lc + 1) * 68 + lrow] = a_r.y;
        As[(lc + 2) * 68 + lrow] = a_r.z;  As[(lc + 3) * 68 + lrow] = a_r.w;
        Bs[(lc + 0) * 132 + lrow] = b_r0.x; Bs[(lc + 1) * 132 + lrow] = b_r0.y;
        Bs[(lc + 2) * 132 + lrow] = b_r0.z; Bs[(lc + 3) * 132 + lrow] = b_r0.w;
        Bs[(lc + 0) * 132 + 64 + lrow] = b_r1.x; Bs[(lc + 1) * 132 + 64 + lrow] = b_r1.y;
        Bs[(lc + 2) * 132 + 64 + lrow] = b_r1.z; Bs[(lc + 3) * 132 + 64 + lrow] = b_r1.w;
    }
    __syncthreads();

#pragma unroll 1
    for (int kt = 0; kt < 7; kt++) {
        const float* As = sm + (kt & 1) * 3200;
        const float* Bs = As + 1088;

        if (kt < 6) {
            a_r  = *(const float4*)(Xp  + (kt + 1) * 16);
            b_r0 = *(const float4*)(Wp0 + (kt + 1) * 16);
            b_r1 = *(const float4*)(Wp1 + (kt + 1) * 16);
        }

#pragma unroll
        for (int kk = 0; kk < 16; kk++) {
            const float4 a = *(const float4*)(As + kk * 68 + ty * 4);
            const ulonglong2 bl = *(const ulonglong2*)(Bs + kk * 132 + tx * 4);
            const ulonglong2 bh = *(const ulonglong2*)(Bs + kk * 132 + 64 + tx * 4);
            const float av[4] = {a.x, a.y, a.z, a.w};
#pragma unroll
            for (int r = 0; r < 4; r++) {
                const ull ar = pkf2(av[r], av[r]);
                acc[r][0] = fmaf32x2(ar, bl.x, acc[r][0]);
                acc[r][1] = fmaf32x2(ar, bl.y, acc[r][1]);
                acc[r][2] = fmaf32x2(ar, bh.x, acc[r][2]);
                acc[r][3] = fmaf32x2(ar, bh.y, acc[r][3]);
            }
        }

        if (kt < 6) {
            float* An = sm + ((kt + 1) & 1) * 3200;
            float* Bn = An + 1088;
            An[(lc + 0) * 68 + lrow] = a_r.x;  An[(lc + 1) * 68 + lrow] = a_r.y;
            An[(lc + 2) * 68 + lrow] = a_r.z;  An[(lc + 3) * 68 + lrow] = a_r.w;
            Bn[(lc + 0) * 132 + lrow] = b_r0.x; Bn[(lc + 1) * 132 + lrow] = b_r0.y;
            Bn[(lc + 2) * 132 + lrow] = b_r0.z; Bn[(lc + 3) * 132 + lrow] = b_r0.w;
            Bn[(lc + 0) * 132 + 64 + lrow] = b_r1.x; Bn[(lc + 1) * 132 + 64 + lrow] = b_r1.y;
            Bn[(lc + 2) * 132 + 64 + lrow] = b_r1.z; Bn[(lc + 3) * 132 + 64 + lrow] = b_r1.w;
            __syncthreads();
        }
    }

    float* outb = g_part + (unsigned)s * BATCH * HID;
#pragma unroll
    for (int r = 0; r < 4; r++) {
        float* orow = outb + (unsigned)(bm + ty * 4 + r) * HID + bn;
        float lo, hi;
        unpkf2(acc[r][0], lo, hi); orow[tx * 4]          = lo; orow[tx * 4 + 1]      = hi;
        unpkf2(acc[r][1], lo, hi); orow[tx * 4 + 2]      = lo; orow[tx * 4 + 3]      = hi;
        unpkf2(acc[r][2], lo, hi); orow[64 + tx * 4]     = lo; orow[64 + tx * 4 + 1] = hi;
        unpkf2(acc[r][3], lo, hi); orow[64 + tx * 4 + 2] = lo; orow[64 + tx * 4 + 3] = hi;
    }
}

// ---------------------------------------------------------------------------
// Fused snn (R9 gather + in-t x8 unroll + in-block layer 2):
// one block (256 thr) per batch b; thread owns 4 adjacent neurons.
// Per-t lists padded to x8 with zero-row id -> 8 LDG.128 in flight per warp.
// Accumulation chains identical to R9 (A<-rows 0,2,4,6..; B<-1,3,5,7..).
// ---------------------------------------------------------------------------
__global__ void __launch_bounds__(256, 3) snn_kernel(
    const float* __restrict__ b0,
    const float* __restrict__ b1,
    const float* __restrict__ b2,
    float* __restrict__ out)  // [512,10]
{
    const int b = blockIdx.x;
    const int tid = threadIdx.x;
    const int lane = tid & 31, warp = tid >> 5;   // 8 warps

    __shared__ unsigned       mask1[NT][32];
    __shared__ unsigned short uni_idx[HID];
    __shared__ unsigned       uni_tm[HID];
    __shared__ unsigned short list[NT * LCAP];
    __shared__ int            n0s[NT];
    __shared__ int            segCnt[32], segBal[32], segOff[32], sh_nU;
    __shared__ float          c2part[NT][NOUT];

    // ---- phase 1: combine split-K partials, layer-0 LIF ----
    float4 c0 = *(const float4*)(b0 + 4 * tid);
#pragma unroll
    for (int s = 0; s < KSPLIT; s++) {
        float4 p = *(const float4*)(g_part + ((unsigned)s * BATCH + b) * HID + 4 * tid);
        c0.x += p.x; c0.y += p.y; c0.z += p.z; c0.w += p.w;
    }
    float c0a[4] = {c0.x, c0.y, c0.z, c0.w};
    unsigned tm0[4] = {0u, 0u, 0u, 0u};
    {
        float v0[4] = {0.f, 0.f, 0.f, 0.f};
#pragma unroll
        for (int t = 0; t < NT; t++) {
#pragma unroll
            for (int j = 0; j < 4; j++) {
                v0[j] += (c0a[j] - v0[j]) * 0.5f;
                if (v0[j] >= 1.0f) { tm0[j] |= (1u << t); v0[j] = 0.f; }
            }
        }
    }

    // ---- phase 2a: union list ----
#pragma unroll
    for (int j = 0; j < 4; j++) {
        unsigned bal = __ballot_sync(0xffffffffu, tm0[j] != 0u);
        if (lane == 0) {
            segCnt[warp * 4 + j] = __popc(bal);
            segBal[warp * 4 + j] = (int)bal;
        }
    }
    __syncthreads();
    if (warp == 0) {
        int c = segCnt[lane];
        int inc = c;
#pragma unroll
        for (int d = 1; d < 32; d <<= 1) {
            int y = __shfl_up_sync(0xffffffffu, inc, d);
            if (lane >= d) inc += y;
        }
        segOff[lane] = inc - c;
        if (lane == 31) sh_nU = inc;
    }
    __syncthreads();
#pragma unroll
    for (int j = 0; j < 4; j++) {
        if (tm0[j] != 0u) {
            const int s = warp * 4 + j;
            const int pos = segOff[s] +
                __popc((unsigned)segBal[s] & ((1u << lane) - 1u));
            uni_idx[pos] = (unsigned short)(4 * tid + j);
            uni_tm[pos]  = tm0[j];
        }
    }
    __syncthreads();

    // ---- phase 2b: per-timestep lists, padded to multiple of 8 ----
    const int nU = sh_nU;
#pragma unroll
    for (int h = 0; h < 4; h++) {
        const int t = warp * 4 + h;
        int base = 0;
        for (int c = 0; c < nU; c += 32) {
            const int k = c + lane;
            unsigned tmv = (k < nU) ? uni_tm[k] : 0u;
            bool p = (tmv >> t) & 1u;
            unsigned bal = __ballot_sync(0xffffffffu, p);
            if (p) {
                int pos = base + __popc(bal & ((1u << lane) - 1u));
                if (pos < LCAP - 8) list[t * LCAP + pos] = uni_idx[k];
            }
            base += __popc(bal);
        }
        if (base > LCAP - 8) base = LCAP - 8;
        const int padded = (base + 7) & ~7;
        if (lane == 0) {
            for (int p = base; p < padded; p++)
                list[t * LCAP + p] = (unsigned short)HID;  // zero row
            n0s[t] = padded;
        }
    }
    __syncthreads();

    // ---- phase 3: temporal loop, 8 LDG.128 in flight per iteration ----
    const ull b1p0 = pkf2(b1[4 * tid],     b1[4 * tid + 1]);
    const ull b1p1 = pkf2(b1[4 * tid + 2], b1[4 * tid + 3]);

    float v1[4] = {0.f, 0.f, 0.f, 0.f};
    for (int t = 0; t < NT; t++) {
        const int n8 = n0s[t] >> 3;
        const ushort4* lst4 = (const ushort4*)&list[t * LCAP];
        ull A0 = b1p0, A1 = b1p1, B0 = 0ull, B1 = 0ull;
#pragma unroll 1
        for (int k = 0; k < n8; k++) {
            const ushort4 ia = lst4[2 * k];
            const ushort4 ib = lst4[2 * k + 1];
            ulonglong2 r0 = __ldg((const ulonglong2*)(g_w1t + (unsigned)ia.x * HID) + tid);
            ulonglong2 r1 = __ldg((const ulonglong2*)(g_w1t + (unsigned)ia.y * HID) + tid);
            ulonglong2 r2 = __ldg((const ulonglong2*)(g_w1t + (unsigned)ia.z * HID) + tid);
            ulonglong2 r3 = __ldg((const ulonglong2*)(g_w1t + (unsigned)ia.w * HID) + tid);
            ulonglong2 r4 = __ldg((const ulonglong2*)(g_w1t + (unsigned)ib.x * HID) + tid);
            ulonglong2 r5 = __ldg((const ulonglong2*)(g_w1t + (unsigned)ib.y * HID) + tid);
            ulonglong2 r6 = __ldg((const ulonglong2*)(g_w1t + (unsigned)ib.z * HID) + tid);
            ulonglong2 r7 = __ldg((const ulonglong2*)(g_w1t + (unsigned)ib.w * HID) + tid);
            A0 = addf32x2(A0, r0.x);  A1 = addf32x2(A1, r0.y);
            B0 = addf32x2(B0, r1.x);  B1 = addf32x2(B1, r1.y);
            A0 = addf32x2(A0, r2.x);  A1 = addf32x2(A1, r2.y);
            B0 = addf32x2(B0, r3.x);  B1 = addf32x2(B1, r3.y);
            A0 = addf32x2(A0, r4.x);  A1 = addf32x2(A1, r4.y);
            B0 = addf32x2(B0, r5.x);  B1 = addf32x2(B1, r5.y);
            A0 = addf32x2(A0, r6.x);  A1 = addf32x2(A1, r6.y);
            B0 = addf32x2(B0, r7.x);  B1 = addf32x2(B1, r7.y);
        }
        float c1[4];
        unpkf2(addf32x2(A0, B0), c1[0], c1[1]);
        unpkf2(addf32x2(A1, B1), c1[2], c1[3]);

#pragma unroll
        for (int j = 0; j < 4; j++) {
            v1[j] += (c1[j] - v1[j]) * 0.5f;
            bool s = v1[j] >= 1.0f;
            unsigned bal = __ballot_sync(0xffffffffu, s);
            if (s) v1[j] = 0.f;
            if (lane == 0) mask1[t][warp * 4 + j] = bal;
        }
    }
    __syncthreads();

    // ---- phase 4: layer-2 partial currents (warp w -> t = 4w..4w+3) ----
    // word W, bit l -> neuron 128*(W>>2) + 4*l + (W&3)
#pragma unroll
    for (int h = 0; h < 4; h++) {
        const int t = warp * 4 + h;
        unsigned m = mask1[t][lane];
        float c2 = 0.f;
        unsigned act = __ballot_sync(0xffffffffu, m != 0u);
        while (act) {
            const int src = __ffs(act) - 1;
            act &= act - 1;
            unsigned mw = __shfl_sync(0xffffffffu, m, src);
            const int nb = 128 * (src >> 2) + (src & 3);
            while (mw) {
                const int bit = __ffs(mw) - 1;
                mw &= mw - 1;
                if (lane < NOUT)
                    c2 += g_w2t[(unsigned)(nb + 4 * bit) * 16 + lane];
            }
        }
        if (lane < NOUT) c2part[t][lane] = c2;
    }
    __syncthreads();

    // ---- phase 5: layer-2 LIF recurrence + spike count ----
    if (warp == 0 && lane < NOUT) {
        const float b2r = b2[lane];
        float v2 = 0.f, cnt = 0.f;
#pragma unroll
        for (int t = 0; t < NT; t++) {
            const float c2 = c2part[t][lane] + b2r;
            v2 += (c2 - v2) * 0.5f;
            if (v2 >= 1.0f) { cnt += 1.0f; v2 = 0.f; }
        }
        out[b * NOUT + lane] = cnt;
    }
}

// ---------------------------------------------------------------------------
extern "C" void kernel_launch(void* const* d_in, const int* in_sizes, int n_in,
                              void* d_out, int out_size) {
    const float* x  = (const float*)d_in[0];  // [512,784]
    const float* W0 = (const float*)d_in[1];  // [1024,784]
    const float* b0 = (const float*)d_in[2];  // [1024]
    const float* W1 = (const float*)d_in[3];  // [1024,1024]
    const float* b1 = (const float*)d_in[4];  // [1024]
    const float* W2 = (const float*)d_in[5];  // [10,1024]
    const float* b2 = (const float*)d_in[6];  // [10]
    float* out = (float*)d_out;               // [512,10] float32

    prep_kernel<<<704, 256>>>(x, W0, W1, W2);
    snn_kernel<<<BATCH, 256>>>(b0, b1, b2, out);
}